// round 10
// baseline (speedup 1.0000x reference)
#include <cuda_runtime.h>

#define N_SEG   65536
#define TOTAL   2097152
#define THREADS 64
#define CTAS_PER_SM 20
#define NSM     152
#define GRID    (NSM * CTAS_PER_SM)      /* 3040 CTAs, one resident wave */
#define NWARPS  (GRID * 2)               /* 6080 warps */
#define RPW     345                      /* ceil(TOTAL / NWARPS) rows per warp */

__device__ __forceinline__ int ipr(const void* p, bool is32, int i) {
    return is32 ? __ldg((const int*)p + i) : (int)__ldg((const long long*)p + i);
}

// first i in [0, N_SEG] with indptr[i] >= target
__device__ __forceinline__ int lb(const void* p, bool is32, int target) {
    int lo = 0, hi = N_SEG;
    while (lo < hi) {
        int m = (lo + hi) >> 1;
        if (ipr(p, is32, m) < target) lo = m + 1;
        else hi = m;
    }
    return lo;
}

__device__ __forceinline__ void acc4(float4& a, const float4 v) {
    a.x += v.x; a.y += v.y; a.z += v.z; a.w += v.w;
}

__global__ __launch_bounds__(THREADS, CTAS_PER_SM)
void segment_csr_kernel(const float* __restrict__ x,
                        const void* __restrict__ indptr_raw,
                        float* __restrict__ out) {
    const int w    = blockIdx.x * 2 + (threadIdx.x >> 5);
    const int lane = threadIdx.x & 31;

    // Inline dtype probe: word 65536 exists in both layouts.
    // int32 layout: == TOTAL (last element). int64: == high word of
    // indptr[32768] == 0. One cached broadcast load per warp.
    const bool is32 = (__ldg((const int*)indptr_raw + N_SEG) == TOTAL);

    const int r0 = w * RPW;
    if (r0 >= TOTAL) return;
    const int r1 = min(r0 + RPW, TOTAL);
    const bool lastw = (r1 == TOTAL);   // also owns trailing empty segments

    // Ownership: this warp processes every segment whose START lies in
    // [r0, r1), summing it to its TRUE end (possibly past r1). A segment
    // straddling r0 belongs to the previous warp and is skipped here.
    // => no atomics, no pre-zeroing, each row read exactly once.
    int i = lb(indptr_raw, is32, r0);

    // lane l owns columns [4l,4l+4): each row is one fully-coalesced 512B
    // warp transaction.
    const float4* xr = reinterpret_cast<const float4*>(x) + lane;
    float4* outr = reinterpret_cast<float4*>(out) + lane;

    int start = ipr(indptr_raw, is32, i);
    while (i < N_SEG && (lastw || start < r1)) {
        const int end = ipr(indptr_raw, is32, i + 1);

        float4 a0 = make_float4(0.f, 0.f, 0.f, 0.f);
        float4 a1 = make_float4(0.f, 0.f, 0.f, 0.f);
        float4 a2 = make_float4(0.f, 0.f, 0.f, 0.f);
        float4 a3 = make_float4(0.f, 0.f, 0.f, 0.f);

        int r = start;
        // 4 independent LDG.128 in flight per iteration.
        for (; r + 4 <= end; r += 4) {
            const float4 v0 = __ldcs(xr + (size_t)(r    ) * 32);
            const float4 v1 = __ldcs(xr + (size_t)(r + 1) * 32);
            const float4 v2 = __ldcs(xr + (size_t)(r + 2) * 32);
            const float4 v3 = __ldcs(xr + (size_t)(r + 3) * 32);
            acc4(a0, v0); acc4(a1, v1); acc4(a2, v2); acc4(a3, v3);
        }
        for (; r < end; ++r) {
            acc4(a0, __ldcs(xr + (size_t)r * 32));
        }
        acc4(a0, a1); acc4(a2, a3); acc4(a0, a2);

        __stcs(outr + (size_t)i * 32, a0);

        ++i;
        start = end;
    }
}

extern "C" void kernel_launch(void* const* d_in, const int* in_sizes, int n_in,
                              void* d_out, int out_size) {
    const float* x     = (const float*)d_in[0];
    const void* indptr = d_in[1];
    float* out         = (float*)d_out;

    segment_csr_kernel<<<GRID, THREADS>>>(x, indptr, out);
}

// round 11
// speedup vs baseline: 1.0491x; 1.0491x over previous
#include <cuda_runtime.h>

#define N_SEG   65536
#define TOTAL   2097152
#define THREADS 64
#define CTAS_PER_SM 20
#define NSM     152
#define GRID    (NSM * CTAS_PER_SM)      /* 3040 CTAs, one resident wave */
#define NWARPS  (GRID * 2)               /* 6080 warps */
#define RPW     345                      /* ceil(TOTAL / NWARPS) rows per warp */

// Cross-warp handoff for boundary-straddling segments.
// flag[w]: 0 -> 1 once per launch (producer), reset to 0 by the single consumer.
__device__ float                 g_scratch[NWARPS][128];
__device__ volatile unsigned int g_flag[NWARPS];          // zero-initialized

__device__ __forceinline__ int ipr(const void* p, bool is32, int i) {
    return is32 ? __ldg((const int*)p + i) : (int)__ldg((const long long*)p + i);
}

// first i in [0, N_SEG] with indptr[i] >= target
__device__ __forceinline__ int lb(const void* p, bool is32, int target) {
    int lo = 0, hi = N_SEG;
    while (lo < hi) {
        int m = (lo + hi) >> 1;
        if (ipr(p, is32, m) < target) lo = m + 1;
        else hi = m;
    }
    return lo;
}

__device__ __forceinline__ void acc4(float4& a, const float4 v) {
    a.x += v.x; a.y += v.y; a.z += v.z; a.w += v.w;
}

// Sum rows [lo, hi) of x (float4 lane view), 4 LDG.128 in flight.
__device__ __forceinline__ float4 sum_rows(const float4* __restrict__ xr,
                                           int lo, int hi) {
    float4 a0 = make_float4(0.f, 0.f, 0.f, 0.f);
    float4 a1 = make_float4(0.f, 0.f, 0.f, 0.f);
    float4 a2 = make_float4(0.f, 0.f, 0.f, 0.f);
    float4 a3 = make_float4(0.f, 0.f, 0.f, 0.f);
    int r = lo;
    for (; r + 4 <= hi; r += 4) {
        const float4 v0 = __ldcs(xr + (size_t)(r    ) * 32);
        const float4 v1 = __ldcs(xr + (size_t)(r + 1) * 32);
        const float4 v2 = __ldcs(xr + (size_t)(r + 2) * 32);
        const float4 v3 = __ldcs(xr + (size_t)(r + 3) * 32);
        acc4(a0, v0); acc4(a1, v1); acc4(a2, v2); acc4(a3, v3);
    }
    for (; r < hi; ++r) acc4(a0, __ldcs(xr + (size_t)r * 32));
    acc4(a0, a1); acc4(a2, a3); acc4(a0, a2);
    return a0;
}

__global__ __launch_bounds__(THREADS, CTAS_PER_SM)
void segment_csr_kernel(const float* __restrict__ x,
                        const void* __restrict__ indptr_raw,
                        float* __restrict__ out) {
    const int w    = blockIdx.x * 2 + (threadIdx.x >> 5);
    const int lane = threadIdx.x & 31;

    // Inline dtype probe (word 65536 exists in both layouts):
    // int32: == TOTAL (last element). int64: == high word of indptr[32768] == 0.
    const bool is32 = (__ldg((const int*)indptr_raw + N_SEG) == TOTAL);

    const int r0 = w * RPW;
    if (r0 >= TOTAL) return;
    const int r1 = min(r0 + RPW, TOTAL);
    const bool lastw = (r1 == TOTAL);    // also owns trailing empty segments

    const float4* xr = reinterpret_cast<const float4*>(x) + lane;
    float4* outr = reinterpret_cast<float4*>(out) + lane;

    // First segment starting at or after r0.
    const int A = lb(indptr_raw, is32, r0);

    // Leading straddler: rows [r0, min(end(A-1), r1)) belong to segment A-1,
    // owned by an earlier warp. Publish the partial FIRST (consumers spin on it).
    if (A >= 1 && ipr(indptr_raw, is32, A) > r0) {
        const int e  = ipr(indptr_raw, is32, A);
        const int hi = min(e, r1);
        const float4 part = sum_rows(xr, r0, hi);
        reinterpret_cast<float4*>(g_scratch[w])[lane] = part;
        __threadfence();
        if (lane == 0) g_flag[w] = 1u;
    }

    // Own segments: every segment whose start lies in [r0, r1).
    int i = A;
    int start = ipr(indptr_raw, is32, i);
    while (i < N_SEG && (lastw || start < r1)) {
        const int end = ipr(indptr_raw, is32, i + 1);
        const int hi  = min(end, r1);

        float4 a = sum_rows(xr, start, hi);

        // Segment extends past our range: gather partials from successor warps.
        if (end > r1) {
            int cov = r1;
            int j = w + 1;
            while (cov < end) {
                while (g_flag[j] == 0u) { }   // all warps resident: safe spin
                __threadfence();
                acc4(a, reinterpret_cast<const float4*>(g_scratch[j])[lane]);
                if (lane == 0) g_flag[j] = 0u;  // single consumer resets
                cov = min(end, (j + 1) * RPW);
                ++j;
            }
        }

        __stcs(outr + (size_t)i * 32, a);
        ++i;
        start = end;
    }
}

extern "C" void kernel_launch(void* const* d_in, const int* in_sizes, int n_in,
                              void* d_out, int out_size) {
    const float* x     = (const float*)d_in[0];
    const void* indptr = d_in[1];
    float* out         = (float*)d_out;

    segment_csr_kernel<<<GRID, THREADS>>>(x, indptr, out);
}